// round 3
// baseline (speedup 1.0000x reference)
#include <cuda_runtime.h>
#include <math.h>

#define TT 4
#define BB 16
#define CC 512
#define NN 1024
#define NHEADS 8

// ---------------- device scratch (no allocations allowed) ----------------
__device__ float g_Wqk[CC * 1024];        // [c][0..511 = q_d, 512..1023 = k_d], BN-folded
__device__ float g_Wp[CC * CC];           // [c][d], BN-folded proj
__device__ float g_bqk[1024];
__device__ float g_bp[CC];
__device__ unsigned g_xs_cmask[TT * BB * NN * 16];  // spike mask over channels, [t][b][n][c/32]
__device__ unsigned g_y_cmask[TT * BB * NN * 16];
__device__ float g_attn_fallback[TT * BB * NHEADS * NN];

// ---------------- K0: fold BN into weights ----------------
__global__ void prep_kernel(const float* __restrict__ qw, const float* __restrict__ qg,
                            const float* __restrict__ qb, const float* __restrict__ qm,
                            const float* __restrict__ qv,
                            const float* __restrict__ kw, const float* __restrict__ kg,
                            const float* __restrict__ kb, const float* __restrict__ km,
                            const float* __restrict__ kv,
                            const float* __restrict__ pw, const float* __restrict__ pbias,
                            const float* __restrict__ pg, const float* __restrict__ pb,
                            const float* __restrict__ pm, const float* __restrict__ pv) {
    int idx = blockIdx.x * blockDim.x + threadIdx.x;  // 512*512
    int d = idx & 511;
    int c = idx >> 9;
    float invq = (float)((double)qg[d] / sqrt((double)qv[d] + 1e-5));
    float invk = (float)((double)kg[d] / sqrt((double)kv[d] + 1e-5));
    float invp = (float)((double)pg[d] / sqrt((double)pv[d] + 1e-5));
    g_Wqk[c * 1024 + d]       = qw[d * CC + c] * invq;
    g_Wqk[c * 1024 + 512 + d] = kw[d * CC + c] * invk;
    g_Wp[c * CC + d]          = pw[d * CC + c] * invp;
    if (c == 0) {
        g_bqk[d]       = qb[d] - qm[d] * invq;
        g_bqk[512 + d] = kb[d] - km[d] * invk;
        g_bp[d]        = pbias[d] * invp + pb[d] - pm[d] * invp;
    }
}

// ---------------- K1: LIF over x, pack channel bitmasks ----------------
// block: 1024 threads = 32 c x 32 n tile; grid: b(16) x cblk(16) x nblk(32)
__global__ __launch_bounds__(1024) void lif_x_kernel(const float* __restrict__ x) {
    int tid = threadIdx.x;
    int bid = blockIdx.x;
    int nblk = bid & 31;
    int cblk = (bid >> 5) & 15;
    int b = bid >> 9;
    int c_l = tid >> 5, n_l = tid & 31;
    int c = cblk * 32 + c_l;
    int n = nblk * 32 + n_l;
    __shared__ unsigned sw[32];
    float v = 0.f;
    const float* xp = x + ((size_t)b * CC + c) * NN + n;
#pragma unroll
    for (int t = 0; t < TT; t++) {
        float xv = xp[(size_t)t * BB * CC * NN];
        v = v + (xv - v) * 0.5f;
        bool s = (v >= 1.0f);
        if (s) v = 0.f;
        unsigned bm = __ballot_sync(0xffffffffu, s);  // lanes = n within this c
        if (n_l == 0) sw[c_l] = bm;
        __syncthreads();
        // transpose 32x32 bits -> word over c for each n
        int n2 = tid >> 5, c2 = tid & 31;
        bool bit = (sw[c2] >> n2) & 1u;
        unsigned cword = __ballot_sync(0xffffffffu, bit);  // lanes = c
        if (c2 == 0) {
            g_xs_cmask[(((size_t)(t * BB + b)) * NN + nblk * 32 + n2) * 16 + cblk] = cword;
        }
        __syncthreads();
    }
}

// deterministic active-list build from 16 mask words (warp 0 only)
__device__ __forceinline__ void build_list(const unsigned* mwords, unsigned short* list,
                                           int* nact_s, int lane) {
    unsigned m = (lane < 16) ? mwords[lane] : 0u;
    int cnt = __popc(m);
    int incl = cnt;
#pragma unroll
    for (int d = 1; d < 32; d <<= 1) {
        int v2 = __shfl_up_sync(0xffffffffu, incl, d);
        if (lane >= d) incl += v2;
    }
    int off = incl - cnt;
    int total = __shfl_sync(0xffffffffu, incl, 31);
    if (lane == 0) *nact_s = total;
    int base = lane * 32;
    while (m) {
        int cb = __ffs(m) - 1;
        list[off++] = (unsigned short)(base + cb);
        m &= m - 1;
    }
}

// ---------------- K2: fused sparse q/k GEMM + LIF + qh + attn LIF + y mask ----------------
// one block per (b, n) column; 512 threads, thread tid = channel d for both q and k
__global__ __launch_bounds__(512) void fused_qk_kernel(float* __restrict__ out_attn) {
    int tid = threadIdx.x;
    int lane = tid & 31, warp = tid >> 5;
    int bid = blockIdx.x;
    int n = bid & (NN - 1);
    int b = bid >> 10;

    __shared__ unsigned short list[512];
    __shared__ int nact_s;
    __shared__ unsigned mwords[16];
    __shared__ int qcnt[16];
    __shared__ unsigned attn_bits_s;

    float vq = 0.f, vk = 0.f, va = 0.f;
    const float bq = g_bqk[tid];
    const float bk = g_bqk[512 + tid];

    for (int t = 0; t < TT; t++) {
        size_t colbase = (((size_t)(t * BB + b)) * NN + n) * 16;
        if (tid < 16) mwords[tid] = g_xs_cmask[colbase + tid];
        __syncthreads();
        if (warp == 0) build_list(mwords, list, &nact_s, lane);
        __syncthreads();

        int na = nact_s;
        float aq = bq, ak = bk;
        int i = 0;
        for (; i + 4 <= na; i += 4) {
            int c0 = list[i], c1 = list[i + 1], c2 = list[i + 2], c3 = list[i + 3];
            float q0 = g_Wqk[c0 * 1024 + tid],       k0 = g_Wqk[c0 * 1024 + 512 + tid];
            float q1 = g_Wqk[c1 * 1024 + tid],       k1 = g_Wqk[c1 * 1024 + 512 + tid];
            float q2 = g_Wqk[c2 * 1024 + tid],       k2 = g_Wqk[c2 * 1024 + 512 + tid];
            float q3 = g_Wqk[c3 * 1024 + tid],       k3 = g_Wqk[c3 * 1024 + 512 + tid];
            aq += q0; ak += k0;
            aq += q1; ak += k1;
            aq += q2; ak += k2;
            aq += q3; ak += k3;
        }
        for (; i < na; i++) {
            int c0 = list[i];
            aq += g_Wqk[c0 * 1024 + tid];
            ak += g_Wqk[c0 * 1024 + 512 + tid];
        }

        // LIF(q), LIF(k): v = v + (x - v)/2; spike if v >= 1; hard reset
        vq = vq + (aq - vq) * 0.5f;
        bool sq = (vq >= 1.0f);
        if (sq) vq = 0.f;
        vk = vk + (ak - vk) * 0.5f;
        bool sk = (vk >= 1.0f);
        if (sk) vk = 0.f;

        // qh = sum of q spikes over Dh=64 per head (2 warps per head)
        unsigned qbits = __ballot_sync(0xffffffffu, sq);
        if (lane == 0) qcnt[warp] = __popc(qbits);
        __syncthreads();

        if (warp == 0) {
            bool sa = false;
            if (lane < 8) {
                float qh = (float)(qcnt[2 * lane] + qcnt[2 * lane + 1]);
                va = va + (qh - va) * 0.5f;
                sa = (va >= 0.5f);
                if (sa) va = 0.f;
                out_attn[(((size_t)(t * BB + b)) * NHEADS + lane) * NN + n] = sa ? 1.f : 0.f;
            }
            unsigned ab = __ballot_sync(0xffffffffu, sa);
            if (lane == 0) attn_bits_s = ab;
        }
        __syncthreads();

        bool y = sk && ((attn_bits_s >> (tid >> 6)) & 1u);
        unsigned yw = __ballot_sync(0xffffffffu, y);
        if (lane == 0) g_y_cmask[colbase + warp] = yw;
        __syncthreads();
    }
}

// ---------------- K3: sparse proj GEMM + bias/BN, staged coalesced writes ----------------
// block: (t, b, 16-column group); 512 threads = channel d
__global__ __launch_bounds__(512) void proj_kernel(float* __restrict__ out) {
    int tid = threadIdx.x;
    int lane = tid & 31, warp = tid >> 5;
    int bid = blockIdx.x;  // t*BB*64 + b*64 + ng
    int ng = bid & 63;
    int b = (bid >> 6) & 15;
    int t = bid >> 10;
    int n0 = ng * 16;

    __shared__ float stage[512 * 17];
    __shared__ unsigned short list[512];
    __shared__ int nact_s;
    __shared__ unsigned mwords[16];

    const float bpv = g_bp[tid];

    for (int j = 0; j < 16; j++) {
        int n = n0 + j;
        size_t colbase = (((size_t)(t * BB + b)) * NN + n) * 16;
        if (tid < 16) mwords[tid] = g_y_cmask[colbase + tid];
        __syncthreads();
        if (warp == 0) build_list(mwords, list, &nact_s, lane);
        __syncthreads();
        int na = nact_s;
        float acc = bpv;
        for (int i = 0; i < na; i++) acc += g_Wp[(int)list[i] * CC + tid];
        stage[tid * 17 + j] = acc;
        __syncthreads();
    }

    size_t obase = ((size_t)(t * BB + b)) * CC * NN + n0;
#pragma unroll
    for (int r = 0; r < 16; r++) {
        int idx = r * 512 + tid;
        int d = idx >> 4, j = idx & 15;
        out[obase + (size_t)d * NN + j] = stage[d * 17 + j];
    }
    (void)warp;
}

// ---------------- launch ----------------
extern "C" void kernel_launch(void* const* d_in, const int* in_sizes, int n_in,
                              void* d_out, int out_size) {
    const float* x      = (const float*)d_in[0];
    const float* q_w    = (const float*)d_in[1];
    const float* q_g    = (const float*)d_in[2];
    const float* q_b    = (const float*)d_in[3];
    const float* q_m    = (const float*)d_in[4];
    const float* q_v    = (const float*)d_in[5];
    const float* k_w    = (const float*)d_in[6];
    const float* k_g    = (const float*)d_in[7];
    const float* k_b    = (const float*)d_in[8];
    const float* k_m    = (const float*)d_in[9];
    const float* k_v    = (const float*)d_in[10];
    const float* p_w    = (const float*)d_in[11];
    const float* p_bias = (const float*)d_in[12];
    const float* p_g    = (const float*)d_in[13];
    const float* p_b    = (const float*)d_in[14];
    const float* p_m    = (const float*)d_in[15];
    const float* p_v    = (const float*)d_in[16];

    float* out = (float*)d_out;
    const size_t Y_ELEMS = (size_t)TT * BB * CC * NN;           // 33,554,432
    const size_t A_ELEMS = (size_t)TT * BB * NHEADS * NN;       // 524,288

    float* attn_ptr;
    if ((size_t)out_size >= Y_ELEMS + A_ELEMS) {
        attn_ptr = out + Y_ELEMS;
    } else {
        void* p = nullptr;
        cudaGetSymbolAddress(&p, g_attn_fallback);
        attn_ptr = (float*)p;
    }

    prep_kernel<<<512, 512>>>(q_w, q_g, q_b, q_m, q_v,
                              k_w, k_g, k_b, k_m, k_v,
                              p_w, p_bias, p_g, p_b, p_m, p_v);
    lif_x_kernel<<<16 * 16 * 32, 1024>>>(x);
    fused_qk_kernel<<<BB * NN, 512>>>(attn_ptr);
    proj_kernel<<<TT * BB * 64, 512>>>(out);
}

// round 4
// speedup vs baseline: 1.0038x; 1.0038x over previous
#include <cuda_runtime.h>
#include <math.h>

#define TT 4
#define BB 16
#define CC 512
#define NN 1024
#define NHEADS 8

// ---------------- device scratch (no allocations allowed) ----------------
__device__ float g_Wqk[CC * 1024];        // [c][0..511 = q_d, 512..1023 = k_d], BN-folded
__device__ float g_Wp[CC * CC];           // [c][d], BN-folded proj
__device__ float g_bqk[1024];
__device__ float g_bp[CC];
__device__ unsigned g_xs_cmask[TT * BB * NN * 16];  // spike mask over channels, [t][b][n][c/32]
__device__ unsigned g_y_cmask[TT * BB * NN * 16];
__device__ float g_attn_fallback[TT * BB * NHEADS * NN];

// ---------------- K0: fold BN into weights ----------------
__global__ void prep_kernel(const float* __restrict__ qw, const float* __restrict__ qg,
                            const float* __restrict__ qb, const float* __restrict__ qm,
                            const float* __restrict__ qv,
                            const float* __restrict__ kw, const float* __restrict__ kg,
                            const float* __restrict__ kb, const float* __restrict__ km,
                            const float* __restrict__ kv,
                            const float* __restrict__ pw, const float* __restrict__ pbias,
                            const float* __restrict__ pg, const float* __restrict__ pb,
                            const float* __restrict__ pm, const float* __restrict__ pv) {
    int idx = blockIdx.x * blockDim.x + threadIdx.x;  // 512*512
    int d = idx & 511;
    int c = idx >> 9;
    float invq = (float)((double)qg[d] / sqrt((double)qv[d] + 1e-5));
    float invk = (float)((double)kg[d] / sqrt((double)kv[d] + 1e-5));
    float invp = (float)((double)pg[d] / sqrt((double)pv[d] + 1e-5));
    g_Wqk[c * 1024 + d]       = qw[d * CC + c] * invq;
    g_Wqk[c * 1024 + 512 + d] = kw[d * CC + c] * invk;
    g_Wp[c * CC + d]          = pw[d * CC + c] * invp;
    if (c == 0) {
        g_bqk[d]       = qb[d] - qm[d] * invq;
        g_bqk[512 + d] = kb[d] - km[d] * invk;
        g_bp[d]        = pbias[d] * invp + pb[d] - pm[d] * invp;
    }
}

// ---------------- K1: LIF over x, pack channel bitmasks ----------------
// block: 1024 threads = 32 c x 32 n tile; grid: b(16) x cblk(16) x nblk(32)
__global__ __launch_bounds__(1024) void lif_x_kernel(const float* __restrict__ x) {
    int tid = threadIdx.x;
    int bid = blockIdx.x;
    int nblk = bid & 31;
    int cblk = (bid >> 5) & 15;
    int b = bid >> 9;
    int c_l = tid >> 5, n_l = tid & 31;
    int c = cblk * 32 + c_l;
    int n = nblk * 32 + n_l;
    __shared__ unsigned sw[32];
    float v = 0.f;
    const float* xp = x + ((size_t)b * CC + c) * NN + n;
#pragma unroll
    for (int t = 0; t < TT; t++) {
        float xv = xp[(size_t)t * BB * CC * NN];
        v = v + (xv - v) * 0.5f;
        bool s = (v >= 1.0f);
        if (s) v = 0.f;
        unsigned bm = __ballot_sync(0xffffffffu, s);  // lanes = n within this c
        if (n_l == 0) sw[c_l] = bm;
        __syncthreads();
        // transpose 32x32 bits -> word over c for each n
        int n2 = tid >> 5, c2 = tid & 31;
        bool bit = (sw[c2] >> n2) & 1u;
        unsigned cword = __ballot_sync(0xffffffffu, bit);  // lanes = c
        if (c2 == 0) {
            g_xs_cmask[(((size_t)(t * BB + b)) * NN + nblk * 32 + n2) * 16 + cblk] = cword;
        }
        __syncthreads();
    }
}

// deterministic active-list build from 16 mask words (warp 0 only)
__device__ __forceinline__ void build_list(const unsigned* mwords, unsigned short* list,
                                           int* nact_s, int lane) {
    unsigned m = (lane < 16) ? mwords[lane] : 0u;
    int cnt = __popc(m);
    int incl = cnt;
#pragma unroll
    for (int d = 1; d < 32; d <<= 1) {
        int v2 = __shfl_up_sync(0xffffffffu, incl, d);
        if (lane >= d) incl += v2;
    }
    int off = incl - cnt;
    int total = __shfl_sync(0xffffffffu, incl, 31);
    if (lane == 0) *nact_s = total;
    int base = lane * 32;
    while (m) {
        int cb = __ffs(m) - 1;
        list[off++] = (unsigned short)(base + cb);
        m &= m - 1;
    }
}

// ---------------- K2: fused sparse q/k GEMM + LIF + qh + attn LIF + y mask ----------------
// one block per (b, n) column; 512 threads, thread tid = channel d for both q and k
__global__ __launch_bounds__(512) void fused_qk_kernel(float* __restrict__ out_attn) {
    int tid = threadIdx.x;
    int lane = tid & 31, warp = tid >> 5;
    int bid = blockIdx.x;
    int n = bid & (NN - 1);
    int b = bid >> 10;

    __shared__ unsigned short list[512];
    __shared__ int nact_s;
    __shared__ unsigned mwords[16];
    __shared__ int qcnt[16];
    __shared__ unsigned attn_bits_s;

    float vq = 0.f, vk = 0.f, va = 0.f;
    const float bq = g_bqk[tid];
    const float bk = g_bqk[512 + tid];

    for (int t = 0; t < TT; t++) {
        size_t colbase = (((size_t)(t * BB + b)) * NN + n) * 16;
        if (tid < 16) mwords[tid] = g_xs_cmask[colbase + tid];
        __syncthreads();
        if (warp == 0) build_list(mwords, list, &nact_s, lane);
        __syncthreads();

        int na = nact_s;
        float aq = bq, ak = bk;
        int i = 0;
        for (; i + 4 <= na; i += 4) {
            int c0 = list[i], c1 = list[i + 1], c2 = list[i + 2], c3 = list[i + 3];
            float q0 = g_Wqk[c0 * 1024 + tid],       k0 = g_Wqk[c0 * 1024 + 512 + tid];
            float q1 = g_Wqk[c1 * 1024 + tid],       k1 = g_Wqk[c1 * 1024 + 512 + tid];
            float q2 = g_Wqk[c2 * 1024 + tid],       k2 = g_Wqk[c2 * 1024 + 512 + tid];
            float q3 = g_Wqk[c3 * 1024 + tid],       k3 = g_Wqk[c3 * 1024 + 512 + tid];
            aq += q0; ak += k0;
            aq += q1; ak += k1;
            aq += q2; ak += k2;
            aq += q3; ak += k3;
        }
        for (; i < na; i++) {
            int c0 = list[i];
            aq += g_Wqk[c0 * 1024 + tid];
            ak += g_Wqk[c0 * 1024 + 512 + tid];
        }

        // LIF(q), LIF(k): v = v + (x - v)/2; spike if v >= 1; hard reset
        vq = vq + (aq - vq) * 0.5f;
        bool sq = (vq >= 1.0f);
        if (sq) vq = 0.f;
        vk = vk + (ak - vk) * 0.5f;
        bool sk = (vk >= 1.0f);
        if (sk) vk = 0.f;

        // qh = sum of q spikes over Dh=64 per head (2 warps per head)
        unsigned qbits = __ballot_sync(0xffffffffu, sq);
        if (lane == 0) qcnt[warp] = __popc(qbits);
        __syncthreads();

        if (warp == 0) {
            bool sa = false;
            if (lane < 8) {
                float qh = (float)(qcnt[2 * lane] + qcnt[2 * lane + 1]);
                va = va + (qh - va) * 0.5f;
                sa = (va >= 0.5f);
                if (sa) va = 0.f;
                out_attn[(((size_t)(t * BB + b)) * NHEADS + lane) * NN + n] = sa ? 1.f : 0.f;
            }
            unsigned ab = __ballot_sync(0xffffffffu, sa);
            if (lane == 0) attn_bits_s = ab;
        }
        __syncthreads();

        bool y = sk && ((attn_bits_s >> (tid >> 6)) & 1u);
        unsigned yw = __ballot_sync(0xffffffffu, y);
        if (lane == 0) g_y_cmask[colbase + warp] = yw;
        __syncthreads();
    }
}

// ---------------- K3: sparse proj GEMM + bias/BN, staged coalesced writes ----------------
// block: (t, b, 16-column group); 512 threads = channel d
__global__ __launch_bounds__(512) void proj_kernel(float* __restrict__ out) {
    int tid = threadIdx.x;
    int lane = tid & 31, warp = tid >> 5;
    int bid = blockIdx.x;  // t*BB*64 + b*64 + ng
    int ng = bid & 63;
    int b = (bid >> 6) & 15;
    int t = bid >> 10;
    int n0 = ng * 16;

    __shared__ float stage[512 * 17];
    __shared__ unsigned short list[512];
    __shared__ int nact_s;
    __shared__ unsigned mwords[16];

    const float bpv = g_bp[tid];

    for (int j = 0; j < 16; j++) {
        int n = n0 + j;
        size_t colbase = (((size_t)(t * BB + b)) * NN + n) * 16;
        if (tid < 16) mwords[tid] = g_y_cmask[colbase + tid];
        __syncthreads();
        if (warp == 0) build_list(mwords, list, &nact_s, lane);
        __syncthreads();
        int na = nact_s;
        float acc = bpv;
        for (int i = 0; i < na; i++) acc += g_Wp[(int)list[i] * CC + tid];
        stage[tid * 17 + j] = acc;
        __syncthreads();
    }

    size_t obase = ((size_t)(t * BB + b)) * CC * NN + n0;
#pragma unroll
    for (int r = 0; r < 16; r++) {
        int idx = r * 512 + tid;
        int d = idx >> 4, j = idx & 15;
        out[obase + (size_t)d * NN + j] = stage[d * 17 + j];
    }
    (void)warp;
}

// ---------------- launch ----------------
extern "C" void kernel_launch(void* const* d_in, const int* in_sizes, int n_in,
                              void* d_out, int out_size) {
    const float* x      = (const float*)d_in[0];
    const float* q_w    = (const float*)d_in[1];
    const float* q_g    = (const float*)d_in[2];
    const float* q_b    = (const float*)d_in[3];
    const float* q_m    = (const float*)d_in[4];
    const float* q_v    = (const float*)d_in[5];
    const float* k_w    = (const float*)d_in[6];
    const float* k_g    = (const float*)d_in[7];
    const float* k_b    = (const float*)d_in[8];
    const float* k_m    = (const float*)d_in[9];
    const float* k_v    = (const float*)d_in[10];
    const float* p_w    = (const float*)d_in[11];
    const float* p_bias = (const float*)d_in[12];
    const float* p_g    = (const float*)d_in[13];
    const float* p_b    = (const float*)d_in[14];
    const float* p_m    = (const float*)d_in[15];
    const float* p_v    = (const float*)d_in[16];

    float* out = (float*)d_out;
    const size_t Y_ELEMS = (size_t)TT * BB * CC * NN;           // 33,554,432
    const size_t A_ELEMS = (size_t)TT * BB * NHEADS * NN;       // 524,288

    float* attn_ptr;
    if ((size_t)out_size >= Y_ELEMS + A_ELEMS) {
        attn_ptr = out + Y_ELEMS;
    } else {
        void* p = nullptr;
        cudaGetSymbolAddress(&p, g_attn_fallback);
        attn_ptr = (float*)p;
    }

    prep_kernel<<<512, 512>>>(q_w, q_g, q_b, q_m, q_v,
                              k_w, k_g, k_b, k_m, k_v,
                              p_w, p_bias, p_g, p_b, p_m, p_v);
    lif_x_kernel<<<16 * 16 * 32, 1024>>>(x);
    fused_qk_kernel<<<BB * NN, 512>>>(attn_ptr);
    proj_kernel<<<TT * BB * 64, 512>>>(out);
}

// round 8
// speedup vs baseline: 1.2671x; 1.2624x over previous
#include <cuda_runtime.h>
#include <math.h>
#include <stdint.h>

#define TT 4
#define BB 16
#define CC 512
#define NN 1024
#define NHEADS 8

// ---------------- device scratch (no allocations allowed) ----------------
__device__ float g_Wp[CC * CC];            // [c][d], BN-folded proj
__device__ float g_bqk[1024];              // [0..511]=q bias, [512..1023]=k bias
__device__ float g_bp[CC];
// per-head weight slices, layout [h][c][e] with e=2*l+j <-> channel 64h + l + 32j
__device__ float g_Wq2[NHEADS * CC * 64];  // 1 MB
__device__ float g_Wk2[NHEADS * CC * 64];  // 1 MB
__device__ unsigned g_xs_cmask[TT * BB * NN * 16];
__device__ unsigned g_y_cmask[TT * BB * NN * 16];
// per-column active-channel list: [col][0]=count, [col][1..127]=channels (ascending)
__device__ unsigned short g_listc[TT * BB * NN * 128];  // 16 MB
__device__ unsigned char g_attn_b[NHEADS * TT * BB * NN];  // attn bits, [h][t][pair]
__device__ float g_attn_fallback[TT * BB * NHEADS * NN];

// ---------------- K0a: fold BN into proj weights + biases ----------------
__global__ void prep_kernel(const float* __restrict__ qg, const float* __restrict__ qb,
                            const float* __restrict__ qm, const float* __restrict__ qv,
                            const float* __restrict__ kg, const float* __restrict__ kb,
                            const float* __restrict__ km, const float* __restrict__ kv,
                            const float* __restrict__ pw, const float* __restrict__ pbias,
                            const float* __restrict__ pg, const float* __restrict__ pb,
                            const float* __restrict__ pm, const float* __restrict__ pv) {
    int idx = blockIdx.x * blockDim.x + threadIdx.x;  // 512*512
    int d = idx & 511;
    int c = idx >> 9;
    float invp = (float)((double)pg[d] / sqrt((double)pv[d] + 1e-5));
    g_Wp[c * CC + d] = pw[d * CC + c] * invp;
    if (c == 0) {
        float invq = (float)((double)qg[d] / sqrt((double)qv[d] + 1e-5));
        float invk = (float)((double)kg[d] / sqrt((double)kv[d] + 1e-5));
        g_bqk[d]       = qb[d] - qm[d] * invq;
        g_bqk[512 + d] = kb[d] - km[d] * invk;
        g_bp[d]        = pbias[d] * invp + pb[d] - pm[d] * invp;
    }
}

// ---------------- K0b: per-head q/k weight slices, BN-folded -------------
__global__ __launch_bounds__(512) void prep_w2_kernel(
        const float* __restrict__ qw, const float* __restrict__ qg, const float* __restrict__ qv,
        const float* __restrict__ kw, const float* __restrict__ kg, const float* __restrict__ kv) {
    int idx = blockIdx.x * blockDim.x + threadIdx.x;  // 262144
    int e = idx & 63;
    int c = (idx >> 6) & 511;
    int h = idx >> 15;
    int d = 64 * h + (e >> 1) + 32 * (e & 1);
    float invq = (float)((double)qg[d] / sqrt((double)qv[d] + 1e-5));
    float invk = (float)((double)kg[d] / sqrt((double)kv[d] + 1e-5));
    g_Wq2[idx] = qw[d * CC + c] * invq;
    g_Wk2[idx] = kw[d * CC + c] * invk;
}

// ---------------- K1: LIF over x, pack channel bitmasks ----------------
__global__ __launch_bounds__(1024) void lif_x_kernel(const float* __restrict__ x) {
    int tid = threadIdx.x;
    int bid = blockIdx.x;
    int nblk = bid & 31;
    int cblk = (bid >> 5) & 15;
    int b = bid >> 9;
    int c_l = tid >> 5, n_l = tid & 31;
    int c = cblk * 32 + c_l;
    int n = nblk * 32 + n_l;
    __shared__ unsigned sw[32];
    float v = 0.f;
    const float* xp = x + ((size_t)b * CC + c) * NN + n;
#pragma unroll
    for (int t = 0; t < TT; t++) {
        float xv = xp[(size_t)t * BB * CC * NN];
        v = v + (xv - v) * 0.5f;
        bool s = (v >= 1.0f);
        if (s) v = 0.f;
        unsigned bm = __ballot_sync(0xffffffffu, s);
        if (n_l == 0) sw[c_l] = bm;
        __syncthreads();
        int n2 = tid >> 5, c2 = tid & 31;
        bool bit = (sw[c2] >> n2) & 1u;
        unsigned cword = __ballot_sync(0xffffffffu, bit);
        if (c2 == 0) {
            g_xs_cmask[(((size_t)(t * BB + b)) * NN + nblk * 32 + n2) * 16 + cblk] = cword;
        }
        __syncthreads();
    }
}

// ---------------- K1b: decode masks into ascending active lists ----------
// one warp per column; 8 warps per block
__global__ __launch_bounds__(256) void list_kernel() {
    int lane = threadIdx.x & 31;
    int col = blockIdx.x * 8 + (threadIdx.x >> 5);   // 0..65535
    unsigned m = (lane < 16) ? g_xs_cmask[(size_t)col * 16 + lane] : 0u;
    int cnt = __popc(m);
    int incl = cnt;
#pragma unroll
    for (int d = 1; d < 32; d <<= 1) {
        int v2 = __shfl_up_sync(0xffffffffu, incl, d);
        if (lane >= d) incl += v2;
    }
    int total = __shfl_sync(0xffffffffu, incl, 31);
    int off = incl - cnt;
    unsigned short* L = g_listc + (size_t)col * 128;
    if (lane == 0) L[0] = (unsigned short)total;
    int base = lane * 32;
    while (m) {
        int cb = __ffs(m) - 1;
        if (off < 127) L[1 + off] = (unsigned short)(base + cb);
        off++;
        m &= m - 1;
    }
}

// ---------------- shared gather core ----------------
// Returns pre-activation sums a0 (channel 64h+lane) and a1 (channel 64h+32+lane)
// from smem-resident head weight slice, for the column's active channels,
// accumulated in ascending-c order starting from bias (matches reference order).
__device__ __forceinline__ void gather_col(const float* __restrict__ sw, int col, int lane,
                                           float bias0, float bias1, float& a0, float& a1) {
    const float2* swp = (const float2*)sw;
    const unsigned short* L = g_listc + (size_t)col * 128;
    int cnt = L[0];
    a0 = bias0; a1 = bias1;
    if (cnt <= 127) {
        int i = 0;
        for (; i + 4 <= cnt; i += 4) {
            int c0 = L[1 + i], c1 = L[2 + i], c2 = L[3 + i], c3 = L[4 + i];
            float2 w0 = swp[c0 * 32 + lane];
            float2 w1 = swp[c1 * 32 + lane];
            float2 w2 = swp[c2 * 32 + lane];
            float2 w3 = swp[c3 * 32 + lane];
            a0 += w0.x; a1 += w0.y;
            a0 += w1.x; a1 += w1.y;
            a0 += w2.x; a1 += w2.y;
            a0 += w3.x; a1 += w3.y;
        }
        for (; i < cnt; i++) {
            float2 w = swp[(int)L[1 + i] * 32 + lane];
            a0 += w.x; a1 += w.y;
        }
    } else {
        // overflow fallback: decode mask words inline (ascending order)
        for (int w = 0; w < 16; w++) {
            unsigned m = g_xs_cmask[(size_t)col * 16 + w];
            int base = w * 32;
            while (m) {
                int c = base + __ffs(m) - 1;
                m &= m - 1;
                float2 ww = swp[c * 32 + lane];
                a0 += ww.x; a1 += ww.y;
            }
        }
    }
}

// ---------------- K2a: q path — gather + LIF(q) + qh + attn LIF ----------
// grid = 8 heads x 128 pair-blocks; block = 1024 threads = 32 warps;
// each warp owns the head's 64 channels and processes 4 pairs serially.
__global__ __launch_bounds__(1024) void q_kernel(float* __restrict__ out_attn) {
    extern __shared__ float sw[];  // 32768 floats = 128 KB
    int tid = threadIdx.x, lane = tid & 31, warp = tid >> 5;
    int h = blockIdx.x >> 7;
    int pb = blockIdx.x & 127;

    {   // load head's q-weight slice
        const float4* src = (const float4*)(g_Wq2 + (size_t)h * 32768);
        float4* dst = (float4*)sw;
        for (int e = tid; e < 8192; e += 1024) dst[e] = src[e];
    }
    __syncthreads();

    float bias0 = g_bqk[64 * h + lane];
    float bias1 = g_bqk[64 * h + 32 + lane];

    for (int pp = 0; pp < 4; pp++) {
        int pg = pb * 128 + warp * 4 + pp;   // pair index (b*1024+n)
        int b = pg >> 10, n = pg & 1023;
        float v0 = 0.f, v1 = 0.f, va = 0.f;
#pragma unroll
        for (int t = 0; t < TT; t++) {
            int col = (t * BB + b) * NN + n;
            float a0, a1;
            gather_col(sw, col, lane, bias0, bias1, a0, a1);
            v0 = v0 + (a0 - v0) * 0.5f;
            bool s0 = (v0 >= 1.0f); if (s0) v0 = 0.f;
            v1 = v1 + (a1 - v1) * 0.5f;
            bool s1 = (v1 >= 1.0f); if (s1) v1 = 0.f;
            unsigned B0 = __ballot_sync(0xffffffffu, s0);
            unsigned B1 = __ballot_sync(0xffffffffu, s1);
            float qh = (float)(__popc(B0) + __popc(B1));
            va = va + (qh - va) * 0.5f;
            bool sa = (va >= 0.5f); if (sa) va = 0.f;
            if (lane == 0) {
                out_attn[(((size_t)(t * BB + b)) * NHEADS + h) * NN + n] = sa ? 1.f : 0.f;
                g_attn_b[((size_t)(h * TT + t)) * (BB * NN) + pg] = sa ? 1 : 0;
            }
        }
    }
}

// ---------------- K2b: k path — gather + LIF(k) + attn-gate -> y mask ----
__global__ __launch_bounds__(1024) void k_kernel() {
    extern __shared__ float sw[];
    int tid = threadIdx.x, lane = tid & 31, warp = tid >> 5;
    int h = blockIdx.x >> 7;
    int pb = blockIdx.x & 127;

    {
        const float4* src = (const float4*)(g_Wk2 + (size_t)h * 32768);
        float4* dst = (float4*)sw;
        for (int e = tid; e < 8192; e += 1024) dst[e] = src[e];
    }
    __syncthreads();

    float bias0 = g_bqk[512 + 64 * h + lane];
    float bias1 = g_bqk[512 + 64 * h + 32 + lane];

    for (int pp = 0; pp < 4; pp++) {
        int pg = pb * 128 + warp * 4 + pp;
        int b = pg >> 10, n = pg & 1023;
        float v0 = 0.f, v1 = 0.f;
#pragma unroll
        for (int t = 0; t < TT; t++) {
            int col = (t * BB + b) * NN + n;
            float a0, a1;
            gather_col(sw, col, lane, bias0, bias1, a0, a1);
            v0 = v0 + (a0 - v0) * 0.5f;
            bool s0 = (v0 >= 1.0f); if (s0) v0 = 0.f;
            v1 = v1 + (a1 - v1) * 0.5f;
            bool s1 = (v1 >= 1.0f); if (s1) v1 = 0.f;
            unsigned B0 = __ballot_sync(0xffffffffu, s0);
            unsigned B1 = __ballot_sync(0xffffffffu, s1);
            unsigned a8 = g_attn_b[((size_t)(h * TT + t)) * (BB * NN) + pg];
            if (!a8) { B0 = 0u; B1 = 0u; }
            if (lane == 0) {
                // channels [64h..64h+32) -> word 2h ; [64h+32..64h+64) -> word 2h+1
                *(uint2*)&g_y_cmask[(size_t)col * 16 + 2 * h] = make_uint2(B0, B1);
            }
        }
    }
}

// deterministic active-list build from 16 mask words (warp 0 only)
__device__ __forceinline__ void build_list(const unsigned* mwords, unsigned short* list,
                                           int* nact_s, int lane) {
    unsigned m = (lane < 16) ? mwords[lane] : 0u;
    int cnt = __popc(m);
    int incl = cnt;
#pragma unroll
    for (int d = 1; d < 32; d <<= 1) {
        int v2 = __shfl_up_sync(0xffffffffu, incl, d);
        if (lane >= d) incl += v2;
    }
    int off = incl - cnt;
    int total = __shfl_sync(0xffffffffu, incl, 31);
    if (lane == 0) *nact_s = total;
    int base = lane * 32;
    while (m) {
        int cb = __ffs(m) - 1;
        list[off++] = (unsigned short)(base + cb);
        m &= m - 1;
    }
}

// ---------------- K3: sparse proj GEMM + bias/BN, staged coalesced writes
__global__ __launch_bounds__(512) void proj_kernel(float* __restrict__ out) {
    int tid = threadIdx.x;
    int lane = tid & 31, warp = tid >> 5;
    int bid = blockIdx.x;
    int ng = bid & 63;
    int b = (bid >> 6) & 15;
    int t = bid >> 10;
    int n0 = ng * 16;

    __shared__ float stage[512 * 17];
    __shared__ unsigned short list[512];
    __shared__ int nact_s;
    __shared__ unsigned mwords[16];

    const float bpv = g_bp[tid];

    for (int jj = 0; jj < 16; jj++) {
        int n = n0 + jj;
        size_t colbase = (((size_t)(t * BB + b)) * NN + n) * 16;
        if (tid < 16) mwords[tid] = g_y_cmask[colbase + tid];
        __syncthreads();
        if (warp == 0) build_list(mwords, list, &nact_s, lane);
        __syncthreads();
        int na = nact_s;
        float acc = bpv;
        for (int i = 0; i < na; i++) acc += g_Wp[(int)list[i] * CC + tid];
        stage[tid * 17 + jj] = acc;
        __syncthreads();
    }

    size_t obase = ((size_t)(t * BB + b)) * CC * NN + n0;
#pragma unroll
    for (int r = 0; r < 16; r++) {
        int idx = r * 512 + tid;
        int d = idx >> 4, jj = idx & 15;
        out[obase + (size_t)d * NN + jj] = stage[d * 17 + jj];
    }
}

// ---------------- launch ----------------
extern "C" void kernel_launch(void* const* d_in, const int* in_sizes, int n_in,
                              void* d_out, int out_size) {
    const float* x      = (const float*)d_in[0];
    const float* q_w    = (const float*)d_in[1];
    const float* q_g    = (const float*)d_in[2];
    const float* q_b    = (const float*)d_in[3];
    const float* q_m    = (const float*)d_in[4];
    const float* q_v    = (const float*)d_in[5];
    const float* k_w    = (const float*)d_in[6];
    const float* k_g    = (const float*)d_in[7];
    const float* k_b    = (const float*)d_in[8];
    const float* k_m    = (const float*)d_in[9];
    const float* k_v    = (const float*)d_in[10];
    const float* p_w    = (const float*)d_in[11];
    const float* p_bias = (const float*)d_in[12];
    const float* p_g    = (const float*)d_in[13];
    const float* p_b    = (const float*)d_in[14];
    const float* p_m    = (const float*)d_in[15];
    const float* p_v    = (const float*)d_in[16];

    float* out = (float*)d_out;
    const size_t Y_ELEMS = (size_t)TT * BB * CC * NN;
    const size_t A_ELEMS = (size_t)TT * BB * NHEADS * NN;

    float* attn_ptr;
    if ((size_t)out_size >= Y_ELEMS + A_ELEMS) {
        attn_ptr = out + Y_ELEMS;
    } else {
        void* p = nullptr;
        cudaGetSymbolAddress(&p, g_attn_fallback);
        attn_ptr = (float*)p;
    }

    cudaFuncSetAttribute(q_kernel, cudaFuncAttributeMaxDynamicSharedMemorySize, 131072);
    cudaFuncSetAttribute(k_kernel, cudaFuncAttributeMaxDynamicSharedMemorySize, 131072);

    prep_kernel<<<512, 512>>>(q_g, q_b, q_m, q_v, k_g, k_b, k_m, k_v,
                              p_w, p_bias, p_g, p_b, p_m, p_v);
    prep_w2_kernel<<<512, 512>>>(q_w, q_g, q_v, k_w, k_g, k_v);
    lif_x_kernel<<<16 * 16 * 32, 1024>>>(x);
    list_kernel<<<8192, 256>>>();
    q_kernel<<<NHEADS * 128, 1024, 131072>>>(attn_ptr);
    k_kernel<<<NHEADS * 128, 1024, 131072>>>();
    proj_kernel<<<TT * BB * 64, 512>>>(out);
}